// round 17
// baseline (speedup 1.0000x reference)
#include <cuda_runtime.h>
#include <cstdint>

#define B_   2
#define C_   32
#define T_   64
#define HW_  4096
#define N_   512
#define BN_  (B_*N_)         /* 1024 */
#define GB_  (BN_*2)         /* 2048 gather blocks (2 per sample) */
#define CH_  16
#define FT_  400
#define L_   (FT_*N_)        /* 204800 */
#define CNT_ (B_*L_)         /* 409600 */
#define OUT_OFF_RESULT ((size_t)B_*CH_*L_)  /* 6,553,600 */

// ---- scratch (device globals) ----
__device__ __align__(16) float g_r[B_*T_*HW_];            // 2 MB
// g_f: quad-plane layout. float4 plane p = t*4 + q, index [p][bn]
__device__ __align__(16) float g_f[(size_t)T_*4*BN_*4];   // 4 MB
__device__ __align__(16) float g_part[32*GB_];            // [col][gather block]
__device__ float g_ss[32];                                // sums[16] + sumsqs[16]
__device__ unsigned g_count = 0;

// ---- compile-time lerp stat tables (fp32 ops identical to reference) ----
struct LerpTab { float wl[64]; float A[64]; float Bc[64]; float Cc[64]; };
constexpr LerpTab make_tab() {
    LerpTab tb{};
    const float step = (float)(63.0/399.0);
    for (int t = 0; t < FT_; t++) {
        float pos = (float)t * step;
        int i0 = (int)pos;
        int i1 = (i0 + 1 < T_) ? i0 + 1 : T_ - 1;
        float w = pos - (float)i0;
        float w0 = 1.0f - w;
        if (i1 == i0) {
            tb.wl[i0] += (w0 + w);
            tb.A[i0]  += (w0 + w) * (w0 + w);
        } else {
            tb.wl[i0] += w0;  tb.wl[i1] += w;
            tb.A[i0]  += w0 * w0;
            tb.Bc[i0] += 2.0f * w0 * w;
            tb.Cc[i0] += w * w;
        }
    }
    return tb;
}
__constant__ LerpTab c_tab = make_tab();

// ============================================================================
// k_main: blocks [0,2048) gather path (2 blocks per sample: t-halves);
//         blocks [2048,3072) r path (champion code, unchanged).
// Last gather block folds g_part -> g_ss.
// ============================================================================
__global__ void __launch_bounds__(128, 8) k_main(
    const float* __restrict__ x, const int* __restrict__ coord,
    const float* __restrict__ Wr, const float* __restrict__ br,
    const float* __restrict__ W1, const float* __restrict__ Wf,
    const float* __restrict__ b1, const float* __restrict__ bf)
{
    __shared__ float xg[C_*33];      // 1056: x [c][tt] / Wf stage / r: Wr
    __shared__ float sWt[C_*CH_];    // folded weights [c][o]
    __shared__ float sbe[CH_];
    __shared__ float sf[33*CH_];     // 528: f [tt][o] / W1 stage
    __shared__ float red_s[128];
    __shared__ float red_q[128];
    __shared__ float sbf[C_];
    __shared__ unsigned s_last;

    int bid = blockIdx.x;
    int tid = threadIdx.x;

    if (bid >= GB_) {
        // ---- r path: r[b][t][hw] = Wr . x + br (validated champion code) ----
        if (tid < 32) xg[tid] = Wr[tid];
        __syncthreads();
        int gt = (bid - GB_)*128 + tid;    // 131072 threads, 4 hw each
        int hw4 = gt & 1023;
        int bt  = gt >> 10;
        int b = bt >> 6, t = bt & 63;
        const float4* xp = (const float4*)(x + (size_t)(b*C_*T_ + t)*HW_) + hw4;
        float brv = br[0];
        float4 acc = make_float4(brv, brv, brv, brv);
        #pragma unroll
        for (int cc = 0; cc < 4; cc++) {
            float4 v[8];
            #pragma unroll
            for (int j = 0; j < 8; j++)
                v[j] = xp[(size_t)(cc*8+j)*T_*(HW_/4)];
            #pragma unroll
            for (int j = 0; j < 8; j++) {
                float wc = xg[cc*8+j];
                acc.x += wc*v[j].x; acc.y += wc*v[j].y;
                acc.z += wc*v[j].z; acc.w += wc*v[j].w;
            }
        }
        ((float4*)g_r)[gt] = acc;
        return;
    }

    // ---- gather path: block = (bn, t-half h) ----
    int bn = bid >> 1;
    int h  = bid & 1;
    int t0 = h * 32;
    int b = bn >> 9;
    int idx = coord[bn*2]*64 + coord[bn*2+1];

    // 1056 scattered x loads: element e = c*33 + tt -> x[c][t0+tt] (clamped)
    const float* xp = x + ((size_t)b*C_*T_ + t0)*HW_ + idx;
    float rv[9];
    #pragma unroll
    for (int i = 0; i < 9; i++) {
        int e = tid + i*128;
        if (e < 1056) {
            int c = e / 33, tt = e - c*33;
            int ttc = (t0 + tt > 63) ? (63 - t0) : tt;   // only clamps h=1,tt=32 (unused)
            rv[i] = xp[((size_t)c*T_ + ttc)*HW_];
        }
    }

    // stage W1 -> sf[0:512], Wf -> xg[0:1024], bf -> sbf
    for (int e = tid; e < CH_*C_; e += 128) sf[e] = W1[e];
    for (int e = tid; e < C_*C_; e += 128) xg[e] = Wf[e];
    if (tid < 32) sbf[tid] = bf[tid];
    __syncthreads();

    // fold: sWt[c][o] = sum_k W1[o][k] * Wf[k][c]   (same exprs as champion)
    #pragma unroll
    for (int i = 0; i < 4; i++) {
        int e = tid*4 + i;
        int c = e >> 4, o = e & 15;
        float a = 0.f;
        #pragma unroll
        for (int k = 0; k < 32; k++) a += sf[o*32+k] * xg[k*32 + c];
        sWt[c*CH_+o] = a;
    }
    if (tid < CH_) {
        float bb = b1[tid];
        #pragma unroll
        for (int k = 0; k < 32; k++) bb += sf[tid*32+k] * sbf[k];
        sbe[tid] = bb;
    }
    __syncthreads();
    // park gathered x into xg [c][tt]
    #pragma unroll
    for (int i = 0; i < 9; i++) {
        int e = tid + i*128;
        if (e < 1056) xg[e] = rv[i];
    }
    __syncthreads();

    // f[tt][o] = beff[o] + sum_c Wt[c][o] * xg[c][tt]   (ascending c: bitwise
    // identical to champion, incl. the boundary t=32 recomputed by both halves)
    #pragma unroll
    for (int i = 0; i < 5; i++) {
        int e = tid + i*128;
        if (e < 33*CH_) {
            int tt = e >> 4, o = e & 15;
            float a = sbe[o];
            #pragma unroll
            for (int c = 0; c < 32; c++) a += sWt[c*CH_+o] * xg[c*33+tt];
            sf[e] = a;
        }
    }
    __syncthreads();

    // store f rows t0..t0+31 -> g_f quad-plane layout (128 float4s)
    {
        float4* gf4 = (float4*)g_f;
        const float4* sf4 = (const float4*)sf;
        int tl = tid >> 2, q = tid & 3;          // tl 0..31
        gf4[(size_t)((t0+tl)*4 + q)*BN_ + bn] = sf4[tid];
    }

    // table-based stats over this block's i-range [t0, t0+32)
    {
        int o = tid & 15, j = tid >> 4;          // j 0..7
        float s_acc = 0.f, q_acc = 0.f;
        #pragma unroll
        for (int k = 0; k < 4; k++) {
            int il = j*4 + k;                    // local i 0..31
            int gi = t0 + il;
            int i1l = (gi < 63) ? il + 1 : il;   // h=0: <=32 (valid); h=1 edge: 31
            float fi  = sf[il*16 + o];
            float fi1 = sf[i1l*16 + o];
            s_acc += c_tab.wl[gi] * fi;
            q_acc += c_tab.A[gi]*fi*fi + c_tab.Bc[gi]*fi*fi1 + c_tab.Cc[gi]*fi1*fi1;
        }
        red_s[j*16 + o] = s_acc;
        red_q[j*16 + o] = q_acc;
    }
    __syncthreads();
    if (tid < 32) {
        int c = tid & 15;
        const float* src = (tid < 16) ? red_s : red_q;
        float tot = 0.f;
        #pragma unroll
        for (int jj = 0; jj < 8; jj++) tot += src[jj*16 + c];
        g_part[tid*GB_ + bid] = tot;
    }

    // last gather block folds g_part -> g_ss
    __threadfence();
    if (tid == 0) s_last = (atomicAdd(&g_count, 1u) == (GB_-1)) ? 1u : 0u;
    __syncthreads();
    if (s_last) {
        int c = tid >> 2, qd = tid & 3;
        const float4* p = (const float4*)(g_part + c*GB_) + qd*128;
        float acc = 0.f;
        #pragma unroll 16
        for (int k = 0; k < 128; k++) {
            float4 v4 = p[k];
            acc += (v4.x + v4.y) + (v4.z + v4.w);
        }
        red_s[tid] = acc;
        __syncthreads();
        if (tid < 32) {
            g_ss[tid] = (red_s[tid*4] + red_s[tid*4+1])
                      + (red_s[tid*4+2] + red_s[tid*4+3]);
            if (tid == 0) g_count = 0;   // reset for next graph replay
        }
    }
}

// ============================================================================
// k_fin: blocks [0,1600) -> 2-cell BN+ReLU+W2 epilogue;
//        blocks [1600,4800) -> result lerp. (validated: 16.9 us, unchanged)
// ============================================================================
__global__ void __launch_bounds__(128) k_fin(
    const float* __restrict__ gamma, const float* __restrict__ beta,
    const float* __restrict__ W2, const float* __restrict__ b2,
    float* __restrict__ out)
{
    __shared__ float4 sW2[64];
    __shared__ float sb2[CH_], ssc[CH_], ssh[CH_];

    int bid = blockIdx.x;
    int tid = threadIdx.x;

    if (bid >= 1600) {
        int base = (bid - 1600)*128 + tid;           // 0..409599
        #pragma unroll
        for (int hh = 0; hh < 2; hh++) {
            int e = base + hh*409600;
            int hw4 = e & 1023;
            int bt  = e >> 10;
            int t = bt % FT_;
            int b = bt / FT_;
            const float step = (float)(63.0/399.0);
            float pos = (float)t * step;
            int i0 = (int)pos;
            int i1 = min(i0+1, T_-1);
            float w = pos - (float)i0, w0 = 1.f - w;
            float4 a = ((const float4*)(g_r + (b*T_+i0)*HW_))[hw4];
            float4 c = ((const float4*)(g_r + (b*T_+i1)*HW_))[hw4];
            float4 v = make_float4(a.x*w0 + c.x*w, a.y*w0 + c.y*w,
                                   a.z*w0 + c.z*w, a.w*w0 + c.w*w);
            ((float4*)(out + OUT_OFF_RESULT))[e] = v;
        }
        return;
    }

    if (tid < 64) sW2[tid] = ((const float4*)W2)[tid];
    if (tid < CH_) {
        int o = tid;
        sb2[o] = b2[o];
        float mean = g_ss[o]    * (1.f/(float)CNT_);
        float var  = g_ss[o+16] * (1.f/(float)CNT_) - mean*mean;
        float sc = gamma[o] * rsqrtf(var + 1e-5f);
        ssc[o] = sc;
        ssh[o] = beta[o] - mean*sc;
    }
    __syncthreads();

    int b = (bid >= 800) ? 1 : 0;
    int slab = bid - b*800;                // 0..799
    int l0 = slab * 256;
    int t = l0 >> 9;
    int n0 = l0 & (N_-1);
    const float step = (float)(63.0/399.0);
    float pos = (float)t * step;
    int i0 = (int)pos;
    int i1 = min(i0+1, T_-1);
    float w = pos - (float)i0, w0 = 1.f - w;

    const float4* gf4 = (const float4*)g_f;
    float hr[2][CH_];
    #pragma unroll
    for (int j = 0; j < 2; j++) {
        int bn = b*N_ + n0 + tid + j*128;
        #pragma unroll
        for (int q = 0; q < 4; q++) {
            float4 av = gf4[(size_t)(i0*4+q)*BN_ + bn];
            float4 cv = gf4[(size_t)(i1*4+q)*BN_ + bn];
            hr[j][q*4+0] = fmaxf(ssc[q*4+0]*(av.x*w0 + cv.x*w) + ssh[q*4+0], 0.f);
            hr[j][q*4+1] = fmaxf(ssc[q*4+1]*(av.y*w0 + cv.y*w) + ssh[q*4+1], 0.f);
            hr[j][q*4+2] = fmaxf(ssc[q*4+2]*(av.z*w0 + cv.z*w) + ssh[q*4+2], 0.f);
            hr[j][q*4+3] = fmaxf(ssc[q*4+3]*(av.w*w0 + cv.w*w) + ssh[q*4+3], 0.f);
        }
    }

    float* outp = out + (size_t)b*CH_*L_ + (size_t)t*N_ + n0 + tid;
    #pragma unroll
    for (int o2 = 0; o2 < CH_; o2++) {
        float4 wa = sW2[o2*4+0], wb = sW2[o2*4+1], wc = sW2[o2*4+2], wd = sW2[o2*4+3];
        float bb = sb2[o2];
        #pragma unroll
        for (int j = 0; j < 2; j++) {
            float acc = bb;
            acc += wa.x*hr[j][0];  acc += wa.y*hr[j][1];
            acc += wa.z*hr[j][2];  acc += wa.w*hr[j][3];
            acc += wb.x*hr[j][4];  acc += wb.y*hr[j][5];
            acc += wb.z*hr[j][6];  acc += wb.w*hr[j][7];
            acc += wc.x*hr[j][8];  acc += wc.y*hr[j][9];
            acc += wc.z*hr[j][10]; acc += wc.w*hr[j][11];
            acc += wd.x*hr[j][12]; acc += wd.y*hr[j][13];
            acc += wd.z*hr[j][14]; acc += wd.w*hr[j][15];
            outp[(size_t)o2*L_ + j*128] = acc;
        }
    }
}

extern "C" void kernel_launch(void* const* d_in, const int* in_sizes, int n_in,
                              void* d_out, int out_size) {
    const float* x     = (const float*)d_in[0];
    const int*   coord = (const int*)  d_in[1];
    const float* Wf    = (const float*)d_in[2];
    const float* bf    = (const float*)d_in[3];
    const float* Wr    = (const float*)d_in[4];
    const float* br    = (const float*)d_in[5];
    const float* W1    = (const float*)d_in[6];
    const float* b1    = (const float*)d_in[7];
    const float* gamma = (const float*)d_in[8];
    const float* beta  = (const float*)d_in[9];
    const float* W2    = (const float*)d_in[10];
    const float* b2    = (const float*)d_in[11];
    float* out = (float*)d_out;

    k_main<<<3072, 128>>>(x, coord, Wr, br, W1, Wf, b1, bf);
    k_fin <<<4800, 128>>>(gamma, beta, W2, b2, out);
}